// round 10
// baseline (speedup 1.0000x reference)
#include <cuda_runtime.h>
#include <cuda_bf16.h>
#include <math.h>

// Problem constants
#define BB   2
#define SS   2048
#define DD   1024
#define HH   16
#define DHH  64
#define INNER 2730
#define ROWS_TOT (BB*SS)          // 4096
#define MODW 6144                 // 6*D

// ---------------- scratch buffers (device globals; no allocation) ----------
__device__ float g_mod[BB * MODW];
__device__ float g_x  [(size_t)ROWS_TOT * DD];        // LN-modulated x (reused for y)
__device__ float g_qkv[(size_t)ROWS_TOT * 3 * DD];    // qkv (rope/l2norm in place)
__device__ float g_attn[(size_t)ROWS_TOT * DD];       // attention output [b,s,h*64+d]
__device__ float g_proj[(size_t)ROWS_TOT * DD];       // proj / ffn-out scratch
__device__ float g_tok2[(size_t)ROWS_TOT * DD];       // tokens after attn residual
__device__ float g_h  [(size_t)ROWS_TOT * 2 * INNER]; // ffn_in output
__device__ float g_u  [(size_t)ROWS_TOT * INNER];     // swiglu output

// ---------------- mod = silu(cond) @ w_mod + b_mod --------------------------
__global__ __launch_bounds__(256) void mod_kernel(
    const float* __restrict__ cond, const float* __restrict__ w,
    const float* __restrict__ b, float* __restrict__ mod)
{
    __shared__ float sc[DD];
    int bb = blockIdx.y;
    for (int i = threadIdx.x; i < DD; i += 256) {
        float v = cond[bb * DD + i];
        sc[i] = v / (1.f + __expf(-v));
    }
    __syncthreads();
    int col = blockIdx.x * 256 + threadIdx.x;
    float a0 = 0.f, a1 = 0.f, a2 = 0.f, a3 = 0.f;
    #pragma unroll 4
    for (int i = 0; i < DD; i += 4) {
        a0 += sc[i    ] * w[(size_t)(i    ) * MODW + col];
        a1 += sc[i + 1] * w[(size_t)(i + 1) * MODW + col];
        a2 += sc[i + 2] * w[(size_t)(i + 2) * MODW + col];
        a3 += sc[i + 3] * w[(size_t)(i + 3) * MODW + col];
    }
    mod[bb * MODW + col] = a0 + a1 + a2 + a3 + b[col];
}

// ---------------- LayerNorm + modulate --------------------------------------
__global__ __launch_bounds__(256) void ln_mod_kernel(
    const float* __restrict__ x, const float* __restrict__ mod,
    float* __restrict__ y, int shift_off, int scale_off)
{
    int row = blockIdx.x;
    int b = row >> 11;                   // row / 2048
    const float* xr = x + (size_t)row * DD;
    float s = 0.f, s2 = 0.f;
    for (int i = threadIdx.x; i < DD; i += 256) {
        float v = xr[i]; s += v; s2 += v * v;
    }
    #pragma unroll
    for (int o = 16; o; o >>= 1) {
        s  += __shfl_xor_sync(~0u, s,  o);
        s2 += __shfl_xor_sync(~0u, s2, o);
    }
    __shared__ float rs[8], rs2[8];
    int w = threadIdx.x >> 5, lane = threadIdx.x & 31;
    if (lane == 0) { rs[w] = s; rs2[w] = s2; }
    __syncthreads();
    if (threadIdx.x == 0) {
        float a = 0.f, a2 = 0.f;
        #pragma unroll
        for (int i = 0; i < 8; i++) { a += rs[i]; a2 += rs2[i]; }
        rs[0] = a; rs2[0] = a2;
    }
    __syncthreads();
    float mean = rs[0] * (1.f / DD);
    float var  = rs2[0] * (1.f / DD) - mean * mean;
    float rstd = rsqrtf(var + 1e-5f);
    const float* mo = mod + b * MODW;
    float* yr = y + (size_t)row * DD;
    for (int i = threadIdx.x; i < DD; i += 256) {
        float v = (xr[i] - mean) * rstd;
        yr[i] = v * (1.f + mo[scale_off + i]) + mo[shift_off + i];
    }
}

// ---------------- SGEMM: C[M,N] = A[M,K] @ W[K,N] + bias --------------------
__global__ __launch_bounds__(256) void sgemm_bias(
    const float* __restrict__ A, const float* __restrict__ Bm,
    const float* __restrict__ bias, float* __restrict__ C,
    int M, int N, int K)
{
    constexpr int BM = 128, BN = 128, BK = 8, TM = 8, TN = 8;
    __shared__ float As[BK][BM];
    __shared__ float Bs[BK][BN];
    int tid = threadIdx.x;
    int tx = tid & 15, ty = tid >> 4;
    int row0 = blockIdx.y * BM;
    int col0 = blockIdx.x * BN;
    float acc[TM][TN] = {};
    int aRow = tid >> 1;          // 0..127
    int aCol = (tid & 1) * 4;     // 0 or 4
    int bRow = tid >> 5;          // 0..7
    int bCol = (tid & 31) * 4;    // 0..124

    for (int kt = 0; kt < K; kt += BK) {
        #pragma unroll
        for (int i = 0; i < 4; i++) {
            int kk = kt + aCol + i;
            As[aCol + i][aRow] = (kk < K) ? A[(size_t)(row0 + aRow) * K + kk] : 0.f;
        }
        int kb = kt + bRow;
        const float* brow = Bm + (size_t)kb * N;
        #pragma unroll
        for (int i = 0; i < 4; i++) {
            int cc = col0 + bCol + i;
            Bs[bRow][bCol + i] = (kb < K && cc < N) ? brow[cc] : 0.f;
        }
        __syncthreads();
        #pragma unroll
        for (int k = 0; k < BK; k++) {
            float ra[TM], rb[TN];
            #pragma unroll
            for (int i = 0; i < TM; i++) ra[i] = As[k][ty * TM + i];
            #pragma unroll
            for (int j = 0; j < TN; j++) rb[j] = Bs[k][tx * TN + j];
            #pragma unroll
            for (int i = 0; i < TM; i++)
                #pragma unroll
                for (int j = 0; j < TN; j++)
                    acc[i][j] += ra[i] * rb[j];
        }
        __syncthreads();
    }
    #pragma unroll
    for (int i = 0; i < TM; i++) {
        int r = row0 + ty * TM + i;
        if (r >= M) continue;
        #pragma unroll
        for (int j = 0; j < TN; j++) {
            int c = col0 + tx * TN + j;
            if (c < N) C[(size_t)r * N + c] = acc[i][j] + bias[c];
        }
    }
}

// ---------------- RoPE + l2norm (in-place on q,k slices of qkv) -------------
__global__ __launch_bounds__(256) void rope_l2_kernel(float* __restrict__ qkv)
{
    int gw = (blockIdx.x * 256 + threadIdx.x) >> 5;    // global warp id
    int lane = threadIdx.x & 31;
    // gw encodes (bs, h, which): total B*S*H*2 = 131072
    int which = gw & 1;
    int h = (gw >> 1) & (HH - 1);
    int bs = gw >> 5;   // gw / (2*H) with H=16
    float* base = qkv + (size_t)bs * (3 * DD) + which * DD + h * DHH;
    int pos = bs & (SS - 1);   // bs % 2048

    float2 p = reinterpret_cast<float2*>(base)[lane];
    float inv = __expf(-((float)lane * (1.f / 32.f)) * 9.210340371976184f); // ln(1e4)
    float th = (float)pos * inv;
    float sn, cs;
    sincosf(th, &sn, &cs);
    float re = p.x * cs - p.y * sn;
    float ro = p.x * sn + p.y * cs;
    float ssq = re * re + ro * ro;
    #pragma unroll
    for (int o = 16; o; o >>= 1) ssq += __shfl_xor_sync(~0u, ssq, o);
    float n = sqrtf(ssq);
    float sc = 1.f / fmaxf(n, 1e-12f);
    if (which == 0) sc *= 0.125f;        // fold DH^-0.5 into q
    float2 out; out.x = re * sc; out.y = ro * sc;
    reinterpret_cast<float2*>(base)[lane] = out;
}

// ---------------- Flash attention (fp32, warp-per-query-row) ----------------
__global__ __launch_bounds__(256) void attn_kernel(
    const float* __restrict__ qkv, float* __restrict__ out)
{
    constexpr int RW = 8, TK = 32;
    __shared__ float Ks[TK][DHH + 1];
    __shared__ float Vs[TK][DHH + 1];
    __shared__ float Qs[RW][DHH];
    __shared__ float Ps[RW][TK];

    int w = threadIdx.x >> 5, lane = threadIdx.x & 31;
    int bid = blockIdx.x;
    int rowTile = bid & (SS / RW - 1);       // bid % 256
    int bh = bid >> 8;                        // bid / 256
    int h = bh & (HH - 1);
    int b = bh >> 4;
    int q0 = rowTile * RW;

    for (int i = threadIdx.x; i < RW * DHH; i += 256) {
        int r = i >> 6, d = i & 63;
        Qs[r][d] = qkv[((size_t)(b * SS + q0 + r)) * (3 * DD) + h * DHH + d];
    }
    __syncthreads();

    // hoist this warp's query row into registers
    float qr[DHH];
    #pragma unroll
    for (int d = 0; d < DHH; d++) qr[d] = Qs[w][d];

    float m = -1e30f, l = 0.f, acc0 = 0.f, acc1 = 0.f;

    for (int t0 = 0; t0 < SS; t0 += TK) {
        for (int i = threadIdx.x; i < TK * DHH; i += 256) {
            int r = i >> 6, d = i & 63;
            size_t base = ((size_t)(b * SS + t0 + r)) * (3 * DD) + h * DHH + d;
            Ks[r][d] = qkv[base + DD];
            Vs[r][d] = qkv[base + 2 * DD];
        }
        __syncthreads();

        float s = 0.f;
        #pragma unroll
        for (int d = 0; d < DHH; d++) s += qr[d] * Ks[lane][d];

        float mt = s;
        #pragma unroll
        for (int o = 16; o; o >>= 1) mt = fmaxf(mt, __shfl_xor_sync(~0u, mt, o));
        float mn = fmaxf(m, mt);
        float alpha = __expf(m - mn);
        float p = __expf(s - mn);
        float ps = p;
        #pragma unroll
        for (int o = 16; o; o >>= 1) ps += __shfl_xor_sync(~0u, ps, o);
        l = l * alpha + ps;
        acc0 *= alpha; acc1 *= alpha;
        m = mn;
        Ps[w][lane] = p;
        __syncwarp();
        #pragma unroll
        for (int j = 0; j < TK; j++) {
            float pj = Ps[w][j];
            acc0 += pj * Vs[j][lane];
            acc1 += pj * Vs[j][lane + 32];
        }
        __syncthreads();
    }
    float invl = 1.f / l;
    size_t o = ((size_t)(b * SS + q0 + w)) * DD + h * DHH;
    out[o + lane]      = acc0 * invl;
    out[o + lane + 32] = acc1 * invl;
}

// ---------------- residual + gate: out = base + gate[col]*add ---------------
__global__ __launch_bounds__(256) void resgate_kernel(
    const float* __restrict__ base, const float* __restrict__ add,
    const float* __restrict__ mod, int goff, float* __restrict__ out)
{
    size_t i = (size_t)blockIdx.x * 256 + threadIdx.x;
    int col = (int)(i & (DD - 1));
    int row = (int)(i >> 10);
    int b = row >> 11;
    out[i] = base[i] + mod[b * MODW + goff + col] * add[i];
}

// ---------------- swiglu: u = value * silu(gate) ----------------------------
__global__ __launch_bounds__(256) void swiglu_kernel(
    const float* __restrict__ h, float* __restrict__ u)
{
    size_t i = (size_t)blockIdx.x * 256 + threadIdx.x;
    if (i >= (size_t)ROWS_TOT * INNER) return;
    int row = (int)(i / INNER), col = (int)(i % INNER);
    const float* hr = h + (size_t)row * (2 * INNER);
    float v = hr[col];
    float g = hr[INNER + col];
    u[i] = v * (g / (1.f + __expf(-g)));
}

// ---------------- launch ----------------------------------------------------
extern "C" void kernel_launch(void* const* d_in, const int* in_sizes, int n_in,
                              void* d_out, int out_size)
{
    const float* tokens = (const float*)d_in[0];
    const float* cond   = (const float*)d_in[1];
    const float* w_qkv  = (const float*)d_in[2];
    const float* b_qkv  = (const float*)d_in[3];
    const float* w_ao   = (const float*)d_in[4];
    const float* b_ao   = (const float*)d_in[5];
    const float* w_fi   = (const float*)d_in[6];
    const float* b_fi   = (const float*)d_in[7];
    const float* w_fo   = (const float*)d_in[8];
    const float* b_fo   = (const float*)d_in[9];
    const float* w_mod  = (const float*)d_in[10];
    const float* b_mod  = (const float*)d_in[11];
    float* out = (float*)d_out;

    float *mod, *x, *qkv, *attn, *proj, *tok2, *hbuf, *ubuf;
    cudaGetSymbolAddress((void**)&mod,  g_mod);
    cudaGetSymbolAddress((void**)&x,    g_x);
    cudaGetSymbolAddress((void**)&qkv,  g_qkv);
    cudaGetSymbolAddress((void**)&attn, g_attn);
    cudaGetSymbolAddress((void**)&proj, g_proj);
    cudaGetSymbolAddress((void**)&tok2, g_tok2);
    cudaGetSymbolAddress((void**)&hbuf, g_h);
    cudaGetSymbolAddress((void**)&ubuf, g_u);

    // 1) modulation vector
    mod_kernel<<<dim3(MODW / 256, BB), 256>>>(cond, w_mod, b_mod, mod);
    // 2) x = modulate(LN(tokens), shift_a, scale_a)
    ln_mod_kernel<<<ROWS_TOT, 256>>>(tokens, mod, x, 0, 1024);
    // 3) qkv
    sgemm_bias<<<dim3(3 * DD / 128, ROWS_TOT / 128), 256>>>(x, w_qkv, b_qkv, qkv,
                                                            ROWS_TOT, 3 * DD, DD);
    // 4) rope + l2norm (q gets *DH^-0.5)
    rope_l2_kernel<<<(BB * SS * HH * 2) / 8, 256>>>(qkv);
    // 5) attention
    attn_kernel<<<BB * HH * (SS / 8), 256>>>(qkv, attn);
    // 6) attn out projection
    sgemm_bias<<<dim3(DD / 128, ROWS_TOT / 128), 256>>>(attn, w_ao, b_ao, proj,
                                                        ROWS_TOT, DD, DD);
    // 7) tokens2 = tokens + gate_a * proj
    resgate_kernel<<<ROWS_TOT * DD / 256, 256>>>(tokens, proj, mod, 2048, tok2);
    // 8) y = modulate(LN(tokens2), shift_m, scale_m)   (reuse x)
    ln_mod_kernel<<<ROWS_TOT, 256>>>(tok2, mod, x, 3072, 4096);
    // 9) ffn_in
    sgemm_bias<<<dim3((2 * INNER + 127) / 128, ROWS_TOT / 128), 256>>>(
        x, w_fi, b_fi, hbuf, ROWS_TOT, 2 * INNER, DD);
    // 10) swiglu
    swiglu_kernel<<<(unsigned)(((size_t)ROWS_TOT * INNER + 255) / 256), 256>>>(hbuf, ubuf);
    // 11) ffn_out
    sgemm_bias<<<dim3(DD / 128, ROWS_TOT / 128), 256>>>(ubuf, w_fo, b_fo, proj,
                                                        ROWS_TOT, DD, INNER);
    // 12) out = tokens2 + gate_m * proj
    resgate_kernel<<<ROWS_TOT * DD / 256, 256>>>(tok2, proj, mod, 5120, out);
}

// round 11
// speedup vs baseline: 1.4442x; 1.4442x over previous
#include <cuda_runtime.h>
#include <cuda_bf16.h>
#include <math.h>

// Problem constants
#define BB   2
#define SS   2048
#define DD   1024
#define HH   16
#define DHH  64
#define INNER 2730
#define ROWS_TOT (BB*SS)          // 4096
#define MODW 6144                 // 6*D

// ---------------- scratch buffers (device globals; no allocation) ----------
__device__ float g_mod[BB * MODW];
__device__ float g_x  [(size_t)ROWS_TOT * DD];        // LN-modulated x (reused for y)
__device__ float g_qkv[(size_t)ROWS_TOT * 3 * DD];    // qkv (rope/l2norm in place)
__device__ float g_attn[(size_t)ROWS_TOT * DD];       // attention output [b,s,h*64+d]
__device__ float g_proj[(size_t)ROWS_TOT * DD];       // proj / ffn-out scratch
__device__ float g_tok2[(size_t)ROWS_TOT * DD];       // tokens after attn residual
__device__ float g_h  [(size_t)ROWS_TOT * 2 * INNER]; // ffn_in output
__device__ float g_u  [(size_t)ROWS_TOT * INNER];     // swiglu output

// ---------------- mod = silu(cond) @ w_mod + b_mod --------------------------
__global__ __launch_bounds__(256) void mod_kernel(
    const float* __restrict__ cond, const float* __restrict__ w,
    const float* __restrict__ b, float* __restrict__ mod)
{
    __shared__ float sc[DD];
    int bb = blockIdx.y;
    for (int i = threadIdx.x; i < DD; i += 256) {
        float v = cond[bb * DD + i];
        sc[i] = v / (1.f + __expf(-v));
    }
    __syncthreads();
    int col = blockIdx.x * 256 + threadIdx.x;
    float a0 = 0.f, a1 = 0.f, a2 = 0.f, a3 = 0.f;
    #pragma unroll 4
    for (int i = 0; i < DD; i += 4) {
        a0 += sc[i    ] * w[(size_t)(i    ) * MODW + col];
        a1 += sc[i + 1] * w[(size_t)(i + 1) * MODW + col];
        a2 += sc[i + 2] * w[(size_t)(i + 2) * MODW + col];
        a3 += sc[i + 3] * w[(size_t)(i + 3) * MODW + col];
    }
    mod[bb * MODW + col] = a0 + a1 + a2 + a3 + b[col];
}

// ---------------- LayerNorm + modulate --------------------------------------
__global__ __launch_bounds__(256) void ln_mod_kernel(
    const float* __restrict__ x, const float* __restrict__ mod,
    float* __restrict__ y, int shift_off, int scale_off)
{
    int row = blockIdx.x;
    int b = row >> 11;                   // row / 2048
    const float* xr = x + (size_t)row * DD;
    float s = 0.f, s2 = 0.f;
    for (int i = threadIdx.x; i < DD; i += 256) {
        float v = xr[i]; s += v; s2 += v * v;
    }
    #pragma unroll
    for (int o = 16; o; o >>= 1) {
        s  += __shfl_xor_sync(~0u, s,  o);
        s2 += __shfl_xor_sync(~0u, s2, o);
    }
    __shared__ float rs[8], rs2[8];
    int w = threadIdx.x >> 5, lane = threadIdx.x & 31;
    if (lane == 0) { rs[w] = s; rs2[w] = s2; }
    __syncthreads();
    if (threadIdx.x == 0) {
        float a = 0.f, a2 = 0.f;
        #pragma unroll
        for (int i = 0; i < 8; i++) { a += rs[i]; a2 += rs2[i]; }
        rs[0] = a; rs2[0] = a2;
    }
    __syncthreads();
    float mean = rs[0] * (1.f / DD);
    float var  = rs2[0] * (1.f / DD) - mean * mean;
    float rstd = rsqrtf(var + 1e-5f);
    const float* mo = mod + b * MODW;
    float* yr = y + (size_t)row * DD;
    for (int i = threadIdx.x; i < DD; i += 256) {
        float v = (xr[i] - mean) * rstd;
        yr[i] = v * (1.f + mo[scale_off + i]) + mo[shift_off + i];
    }
}

// ---------------- TF32 tensor-core GEMM: C = A[M,K] @ B[K,N] + bias ---------
// 128x128 block tile, BK=16, 8 warps (4x2), warp tile 32x64, mma.m16n8k8.tf32
#define TFBM 128
#define TFBN 128
#define TFBK 16
#define ASTRIDE 20     // 20 % 32 == 4*? -> (20*g + t) banks all distinct
#define BSTRIDE 136    // 136 % 32 == 8 -> (8*t + g) banks all distinct

__device__ __forceinline__ unsigned f2tf(float f) {
    unsigned u;
    asm("cvt.rna.tf32.f32 %0, %1;" : "=r"(u) : "f"(f));
    return u;
}

#define MMA_TF32(d, a, b)                                                     \
    asm volatile(                                                             \
        "mma.sync.aligned.m16n8k8.row.col.f32.tf32.tf32.f32 "                 \
        "{%0,%1,%2,%3}, {%4,%5,%6,%7}, {%8,%9}, {%0,%1,%2,%3};"               \
        : "+f"((d)[0]), "+f"((d)[1]), "+f"((d)[2]), "+f"((d)[3])              \
        : "r"((a)[0]), "r"((a)[1]), "r"((a)[2]), "r"((a)[3]),                 \
          "r"((b)[0]), "r"((b)[1]))

__global__ __launch_bounds__(256, 1) void tf32_gemm_bias(
    const float* __restrict__ A, const float* __restrict__ Bm,
    const float* __restrict__ bias, float* __restrict__ C,
    int M, int N, int K)
{
    __shared__ unsigned As[2][TFBM * ASTRIDE];
    __shared__ unsigned Bs[2][TFBK * BSTRIDE];

    const int tid  = threadIdx.x;
    const int lane = tid & 31;
    const int wid  = tid >> 5;
    const int g    = lane >> 2;       // groupID 0..7
    const int t    = lane & 3;        // thread-in-group 0..3
    const int wm   = wid & 3;         // warp M index 0..3  (32 rows each)
    const int wn   = wid >> 2;        // warp N index 0..1  (64 cols each)

    const int row0 = blockIdx.y * TFBM;
    const int col0 = blockIdx.x * TFBN;

    // A global->smem: each thread 4 x float2 (row arow, cols acolb+{0,2,4,6})
    const int arow  = tid >> 1;           // 0..127
    const int acolb = (tid & 1) * 8;      // 0 or 8
    // B global->smem: each thread 2 x float4 (row brow, cols bcolb+{0,4})
    const int brow  = tid >> 4;           // 0..15
    const int bcolb = (tid & 15) * 8;     // 0..120

    float acc[2][8][4];
    #pragma unroll
    for (int i = 0; i < 2; i++)
        #pragma unroll
        for (int j = 0; j < 8; j++)
            #pragma unroll
            for (int q = 0; q < 4; q++) acc[i][j][q] = 0.f;

    float2 a_st[4];
    float4 b_st[2];

    const int nk = (K + TFBK - 1) / TFBK;

    // ---- prologue: load tile 0 ----
    {
        const float* arow_p = A + (size_t)(row0 + arow) * K;
        #pragma unroll
        for (int j = 0; j < 4; j++) {
            int kk = acolb + j * 2;
            a_st[j] = (kk < K) ? *(const float2*)&arow_p[kk] : make_float2(0.f, 0.f);
        }
        #pragma unroll
        for (int j = 0; j < 2; j++) {
            int cc = col0 + bcolb + j * 4;
            b_st[j] = (brow < K && cc < N) ? *(const float4*)&Bm[(size_t)brow * N + cc]
                                           : make_float4(0.f, 0.f, 0.f, 0.f);
        }
        #pragma unroll
        for (int j = 0; j < 4; j++) {
            As[0][arow * ASTRIDE + acolb + j * 2    ] = f2tf(a_st[j].x);
            As[0][arow * ASTRIDE + acolb + j * 2 + 1] = f2tf(a_st[j].y);
        }
        #pragma unroll
        for (int j = 0; j < 2; j++) {
            int o = brow * BSTRIDE + bcolb + j * 4;
            Bs[0][o    ] = f2tf(b_st[j].x);
            Bs[0][o + 1] = f2tf(b_st[j].y);
            Bs[0][o + 2] = f2tf(b_st[j].z);
            Bs[0][o + 3] = f2tf(b_st[j].w);
        }
    }
    __syncthreads();

    int buf = 0;
    for (int it = 1; it <= nk; it++) {
        // prefetch next tile into registers
        if (it < nk) {
            int kt = it * TFBK;
            const float* arow_p = A + (size_t)(row0 + arow) * K;
            #pragma unroll
            for (int j = 0; j < 4; j++) {
                int kk = kt + acolb + j * 2;
                a_st[j] = (kk < K) ? *(const float2*)&arow_p[kk] : make_float2(0.f, 0.f);
            }
            #pragma unroll
            for (int j = 0; j < 2; j++) {
                int kk = kt + brow;
                int cc = col0 + bcolb + j * 4;
                b_st[j] = (kk < K && cc < N) ? *(const float4*)&Bm[(size_t)kk * N + cc]
                                             : make_float4(0.f, 0.f, 0.f, 0.f);
            }
        }

        // compute on current buffer
        #pragma unroll
        for (int ks = 0; ks < 2; ks++) {
            const int k0 = ks * 8;
            unsigned af[2][4], bf[8][2];
            #pragma unroll
            for (int mt = 0; mt < 2; mt++) {
                int mb = (wm * 32 + mt * 16 + g) * ASTRIDE + k0 + t;
                af[mt][0] = As[buf][mb];
                af[mt][1] = As[buf][mb + 8 * ASTRIDE];
                af[mt][2] = As[buf][mb + 4];
                af[mt][3] = As[buf][mb + 8 * ASTRIDE + 4];
            }
            #pragma unroll
            for (int nt = 0; nt < 8; nt++) {
                int nb = (k0 + t) * BSTRIDE + wn * 64 + nt * 8 + g;
                bf[nt][0] = Bs[buf][nb];
                bf[nt][1] = Bs[buf][nb + 4 * BSTRIDE];
            }
            #pragma unroll
            for (int mt = 0; mt < 2; mt++)
                #pragma unroll
                for (int nt = 0; nt < 8; nt++)
                    MMA_TF32(acc[mt][nt], af[mt], bf[nt]);
        }

        // store prefetched tile into other buffer
        if (it < nk) {
            int ob = buf ^ 1;
            #pragma unroll
            for (int j = 0; j < 4; j++) {
                As[ob][arow * ASTRIDE + acolb + j * 2    ] = f2tf(a_st[j].x);
                As[ob][arow * ASTRIDE + acolb + j * 2 + 1] = f2tf(a_st[j].y);
            }
            #pragma unroll
            for (int j = 0; j < 2; j++) {
                int o = brow * BSTRIDE + bcolb + j * 4;
                Bs[ob][o    ] = f2tf(b_st[j].x);
                Bs[ob][o + 1] = f2tf(b_st[j].y);
                Bs[ob][o + 2] = f2tf(b_st[j].z);
                Bs[ob][o + 3] = f2tf(b_st[j].w);
            }
            __syncthreads();
            buf = ob;
        }
    }

    // ---- epilogue: bias add + store (float2) ----
    #pragma unroll
    for (int mt = 0; mt < 2; mt++) {
        int r = row0 + wm * 32 + mt * 16 + g;
        #pragma unroll
        for (int nt = 0; nt < 8; nt++) {
            int c = col0 + wn * 64 + nt * 8 + t * 2;
            if (c < N) {
                float bc0 = bias[c], bc1 = bias[c + 1];
                float2 v0 = make_float2(acc[mt][nt][0] + bc0, acc[mt][nt][1] + bc1);
                float2 v1 = make_float2(acc[mt][nt][2] + bc0, acc[mt][nt][3] + bc1);
                *(float2*)&C[(size_t)r * N + c]       = v0;
                *(float2*)&C[(size_t)(r + 8) * N + c] = v1;
            }
        }
    }
}

// ---------------- RoPE + l2norm (in-place on q,k slices of qkv) -------------
__global__ __launch_bounds__(256) void rope_l2_kernel(float* __restrict__ qkv)
{
    int gw = (blockIdx.x * 256 + threadIdx.x) >> 5;    // global warp id
    int lane = threadIdx.x & 31;
    int which = gw & 1;
    int h = (gw >> 1) & (HH - 1);
    int bs = gw >> 5;   // gw / (2*H) with H=16
    float* base = qkv + (size_t)bs * (3 * DD) + which * DD + h * DHH;
    int pos = bs & (SS - 1);   // bs % 2048

    float2 p = reinterpret_cast<float2*>(base)[lane];
    float inv = __expf(-((float)lane * (1.f / 32.f)) * 9.210340371976184f); // ln(1e4)
    float th = (float)pos * inv;
    float sn, cs;
    sincosf(th, &sn, &cs);
    float re = p.x * cs - p.y * sn;
    float ro = p.x * sn + p.y * cs;
    float ssq = re * re + ro * ro;
    #pragma unroll
    for (int o = 16; o; o >>= 1) ssq += __shfl_xor_sync(~0u, ssq, o);
    float n = sqrtf(ssq);
    float sc = 1.f / fmaxf(n, 1e-12f);
    if (which == 0) sc *= 0.125f;        // fold DH^-0.5 into q
    float2 out; out.x = re * sc; out.y = ro * sc;
    reinterpret_cast<float2*>(base)[lane] = out;
}

// ---------------- Flash attention (fp32, warp-per-query-row) ----------------
__global__ __launch_bounds__(256) void attn_kernel(
    const float* __restrict__ qkv, float* __restrict__ out)
{
    constexpr int RW = 8, TK = 32;
    __shared__ float Ks[TK][DHH + 1];
    __shared__ float Vs[TK][DHH + 1];
    __shared__ float Qs[RW][DHH];
    __shared__ float Ps[RW][TK];

    int w = threadIdx.x >> 5, lane = threadIdx.x & 31;
    int bid = blockIdx.x;
    int rowTile = bid & (SS / RW - 1);       // bid % 256
    int bh = bid >> 8;                        // bid / 256
    int h = bh & (HH - 1);
    int b = bh >> 4;
    int q0 = rowTile * RW;

    for (int i = threadIdx.x; i < RW * DHH; i += 256) {
        int r = i >> 6, d = i & 63;
        Qs[r][d] = qkv[((size_t)(b * SS + q0 + r)) * (3 * DD) + h * DHH + d];
    }
    __syncthreads();

    float qr[DHH];
    #pragma unroll
    for (int d = 0; d < DHH; d++) qr[d] = Qs[w][d];

    float m = -1e30f, l = 0.f, acc0 = 0.f, acc1 = 0.f;

    for (int t0 = 0; t0 < SS; t0 += TK) {
        for (int i = threadIdx.x; i < TK * DHH; i += 256) {
            int r = i >> 6, d = i & 63;
            size_t base = ((size_t)(b * SS + t0 + r)) * (3 * DD) + h * DHH + d;
            Ks[r][d] = qkv[base + DD];
            Vs[r][d] = qkv[base + 2 * DD];
        }
        __syncthreads();

        float s = 0.f;
        #pragma unroll
        for (int d = 0; d < DHH; d++) s += qr[d] * Ks[lane][d];

        float mt = s;
        #pragma unroll
        for (int o = 16; o; o >>= 1) mt = fmaxf(mt, __shfl_xor_sync(~0u, mt, o));
        float mn = fmaxf(m, mt);
        float alpha = __expf(m - mn);
        float p = __expf(s - mn);
        float ps = p;
        #pragma unroll
        for (int o = 16; o; o >>= 1) ps += __shfl_xor_sync(~0u, ps, o);
        l = l * alpha + ps;
        acc0 *= alpha; acc1 *= alpha;
        m = mn;
        Ps[w][lane] = p;
        __syncwarp();
        #pragma unroll
        for (int j = 0; j < TK; j++) {
            float pj = Ps[w][j];
            acc0 += pj * Vs[j][lane];
            acc1 += pj * Vs[j][lane + 32];
        }
        __syncthreads();
    }
    float invl = 1.f / l;
    size_t o = ((size_t)(b * SS + q0 + w)) * DD + h * DHH;
    out[o + lane]      = acc0 * invl;
    out[o + lane + 32] = acc1 * invl;
}

// ---------------- residual + gate: out = base + gate[col]*add ---------------
__global__ __launch_bounds__(256) void resgate_kernel(
    const float* __restrict__ base, const float* __restrict__ add,
    const float* __restrict__ mod, int goff, float* __restrict__ out)
{
    size_t i = (size_t)blockIdx.x * 256 + threadIdx.x;
    int col = (int)(i & (DD - 1));
    int row = (int)(i >> 10);
    int b = row >> 11;
    out[i] = base[i] + mod[b * MODW + goff + col] * add[i];
}

// ---------------- swiglu: u = value * silu(gate) ----------------------------
__global__ __launch_bounds__(256) void swiglu_kernel(
    const float* __restrict__ h, float* __restrict__ u)
{
    size_t i = (size_t)blockIdx.x * 256 + threadIdx.x;
    if (i >= (size_t)ROWS_TOT * INNER) return;
    int row = (int)(i / INNER), col = (int)(i % INNER);
    const float* hr = h + (size_t)row * (2 * INNER);
    float v = hr[col];
    float g = hr[INNER + col];
    u[i] = v * (g / (1.f + __expf(-g)));
}

// ---------------- launch ----------------------------------------------------
extern "C" void kernel_launch(void* const* d_in, const int* in_sizes, int n_in,
                              void* d_out, int out_size)
{
    const float* tokens = (const float*)d_in[0];
    const float* cond   = (const float*)d_in[1];
    const float* w_qkv  = (const float*)d_in[2];
    const float* b_qkv  = (const float*)d_in[3];
    const float* w_ao   = (const float*)d_in[4];
    const float* b_ao   = (const float*)d_in[5];
    const float* w_fi   = (const float*)d_in[6];
    const float* b_fi   = (const float*)d_in[7];
    const float* w_fo   = (const float*)d_in[8];
    const float* b_fo   = (const float*)d_in[9];
    const float* w_mod  = (const float*)d_in[10];
    const float* b_mod  = (const float*)d_in[11];
    float* out = (float*)d_out;

    float *mod, *x, *qkv, *attn, *proj, *tok2, *hbuf, *ubuf;
    cudaGetSymbolAddress((void**)&mod,  g_mod);
    cudaGetSymbolAddress((void**)&x,    g_x);
    cudaGetSymbolAddress((void**)&qkv,  g_qkv);
    cudaGetSymbolAddress((void**)&attn, g_attn);
    cudaGetSymbolAddress((void**)&proj, g_proj);
    cudaGetSymbolAddress((void**)&tok2, g_tok2);
    cudaGetSymbolAddress((void**)&hbuf, g_h);
    cudaGetSymbolAddress((void**)&ubuf, g_u);

    // 1) modulation vector
    mod_kernel<<<dim3(MODW / 256, BB), 256>>>(cond, w_mod, b_mod, mod);
    // 2) x = modulate(LN(tokens), shift_a, scale_a)
    ln_mod_kernel<<<ROWS_TOT, 256>>>(tokens, mod, x, 0, 1024);
    // 3) qkv  (tf32 tensor cores)
    tf32_gemm_bias<<<dim3(3 * DD / TFBN, ROWS_TOT / TFBM), 256>>>(
        x, w_qkv, b_qkv, qkv, ROWS_TOT, 3 * DD, DD);
    // 4) rope + l2norm (q gets *DH^-0.5)
    rope_l2_kernel<<<(BB * SS * HH * 2) / 8, 256>>>(qkv);
    // 5) attention
    attn_kernel<<<BB * HH * (SS / 8), 256>>>(qkv, attn);
    // 6) attn out projection (tf32)
    tf32_gemm_bias<<<dim3(DD / TFBN, ROWS_TOT / TFBM), 256>>>(
        attn, w_ao, b_ao, proj, ROWS_TOT, DD, DD);
    // 7) tokens2 = tokens + gate_a * proj
    resgate_kernel<<<ROWS_TOT * DD / 256, 256>>>(tokens, proj, mod, 2048, tok2);
    // 8) y = modulate(LN(tokens2), shift_m, scale_m)   (reuse x)
    ln_mod_kernel<<<ROWS_TOT, 256>>>(tok2, mod, x, 3072, 4096);
    // 9) ffn_in (tf32)
    tf32_gemm_bias<<<dim3((2 * INNER + TFBN - 1) / TFBN, ROWS_TOT / TFBM), 256>>>(
        x, w_fi, b_fi, hbuf, ROWS_TOT, 2 * INNER, DD);
    // 10) swiglu
    swiglu_kernel<<<(unsigned)(((size_t)ROWS_TOT * INNER + 255) / 256), 256>>>(hbuf, ubuf);
    // 11) ffn_out (tf32)
    tf32_gemm_bias<<<dim3(DD / TFBN, ROWS_TOT / TFBM), 256>>>(
        ubuf, w_fo, b_fo, proj, ROWS_TOT, DD, INNER);
    // 12) out = tokens2 + gate_m * proj
    resgate_kernel<<<ROWS_TOT * DD / 256, 256>>>(tok2, proj, mod, 5120, out);
}